// round 2
// baseline (speedup 1.0000x reference)
#include <cuda_runtime.h>

// AtteMatchLay: multi-perspective cosine matching.
// out[n,p] = dot / (max(sqrt(n1),eps)*max(sqrt(n2),eps))
//   dot = sum_d r[n,d]*m[n,d]*w2[p,d]
//   n1  = sum_d r[n,d]^2      *w2[p,d]
//   n2  = sum_d m[n,d]^2      *w2[p,d]
// Shapes: N=8192 rows, D=768, P=20.

#define PDIM  20
#define NPAIR 10            // P packed as f32x2 pairs
#define DDIM  768
#define WARPS_PER_BLOCK 8
#define EPS 1e-8f

typedef unsigned long long ull;

// ---- f32x2 packed helpers (Blackwell 2x fp32 path; only reachable via PTX) ----
__device__ __forceinline__ ull pack2(float x) {
    ull r; asm("mov.b64 %0, {%1, %1};" : "=l"(r) : "f"(x)); return r;
}
__device__ __forceinline__ ull f2u(float2 f) {
    ull v; asm("mov.b64 %0, {%1, %2};" : "=l"(v) : "f"(f.x), "f"(f.y)); return v;
}
__device__ __forceinline__ float2 u2f(ull v) {
    float2 f; asm("mov.b64 {%0, %1}, %2;" : "=f"(f.x), "=f"(f.y) : "l"(v)); return f;
}
__device__ __forceinline__ void fma2(ull& acc, ull a, ull b) {
    asm("fma.rn.f32x2 %0, %1, %2, %0;" : "+l"(acc) : "l"(a), "l"(b));
}
__device__ __forceinline__ ull add2(ull a, ull b) {
    ull r; asm("add.rn.f32x2 %0, %1, %2;" : "=l"(r) : "l"(a), "l"(b)); return r;
}

// Scratch for squared, pair-packed weights: layout [NPAIR][DDIM] of (w[2j,d]^2, w[2j+1,d]^2)
__device__ ull g_w2[NPAIR * DDIM];

__global__ void prep_w2_kernel(const float* __restrict__ weight) {
    int t = blockIdx.x * blockDim.x + threadIdx.x;
    if (t < NPAIR * DDIM) {
        int j = t / DDIM;
        int d = t - j * DDIM;
        float a = weight[(2 * j) * DDIM + d];
        float b = weight[(2 * j + 1) * DDIM + d];
        float2 f; f.x = a * a; f.y = b * b;
        g_w2[j * DDIM + d] = f2u(f);
    }
}

__global__ void __launch_bounds__(WARPS_PER_BLOCK * 32)
cosmatch_kernel(const float* __restrict__ repres,
                const float* __restrict__ max_att,
                float* __restrict__ out,
                int N) {
    const int tid  = threadIdx.x;
    const int warp = tid >> 5;
    const int lane = tid & 31;
    const int row  = blockIdx.x * WARPS_PER_BLOCK + warp;
    if (row >= N) return;

    const float* rp = repres  + (size_t)row * DDIM;
    const float* mp = max_att + (size_t)row * DDIM;

    ull accd[NPAIR], accr[NPAIR], accm[NPAIR];
#pragma unroll
    for (int j = 0; j < NPAIR; j++) { accd[j] = 0ull; accr[j] = 0ull; accm[j] = 0ull; }

    // Main loop: lane covers d = lane + 32*i, i in [0,24)
#pragma unroll 4
    for (int i = 0; i < DDIM / 32; i++) {
        const int d = lane + 32 * i;
        const float r = rp[d];
        const float m = mp[d];
        const ull rm = pack2(r * m);
        const ull rr = pack2(r * r);
        const ull mm = pack2(m * m);
#pragma unroll
        for (int j = 0; j < NPAIR; j++) {
            const ull w = g_w2[j * DDIM + d];   // L1-resident, 8B lane stride (coalesced)
            fma2(accd[j], rm, w);
            fma2(accr[j], rr, w);
            fma2(accm[j], mm, w);
        }
    }

    // Cross-lane butterfly reduction of 30 packed f32x2 accumulators
#pragma unroll
    for (int mask = 16; mask > 0; mask >>= 1) {
#pragma unroll
        for (int j = 0; j < NPAIR; j++) {
            accd[j] = add2(accd[j], (ull)__shfl_xor_sync(0xFFFFFFFFu, accd[j], mask));
            accr[j] = add2(accr[j], (ull)__shfl_xor_sync(0xFFFFFFFFu, accr[j], mask));
            accm[j] = add2(accm[j], (ull)__shfl_xor_sync(0xFFFFFFFFu, accm[j], mask));
        }
    }

    // Epilogue: lane 0 finishes 20 cosines for this row
    if (lane == 0) {
        float* o = out + (size_t)row * PDIM;
#pragma unroll
        for (int j = 0; j < NPAIR; j++) {
            const float2 dd = u2f(accd[j]);
            const float2 r2 = u2f(accr[j]);
            const float2 m2 = u2f(accm[j]);
            const float dx = fmaxf(sqrtf(r2.x), EPS) * fmaxf(sqrtf(m2.x), EPS);
            const float dy = fmaxf(sqrtf(r2.y), EPS) * fmaxf(sqrtf(m2.y), EPS);
            o[2 * j + 0] = dd.x / dx;
            o[2 * j + 1] = dd.y / dy;
        }
    }
}

extern "C" void kernel_launch(void* const* d_in, const int* in_sizes, int n_in,
                              void* d_out, int out_size) {
    const float* repres  = (const float*)d_in[0];
    const float* max_att = (const float*)d_in[1];
    const float* weight  = (const float*)d_in[2];
    float* out = (float*)d_out;

    const int N = in_sizes[0] / DDIM;   // 8192 for the given shapes

    // Stage 1: square + pair-pack the weights into device scratch
    {
        const int total = NPAIR * DDIM;
        prep_w2_kernel<<<(total + 255) / 256, 256>>>(weight);
    }

    // Stage 2: main fused cosine kernel, one warp per row
    {
        const int threads = WARPS_PER_BLOCK * 32;
        const int blocks  = (N + WARPS_PER_BLOCK - 1) / WARPS_PER_BLOCK;
        cosmatch_kernel<<<blocks, threads>>>(repres, max_att, out, N);
    }
}

// round 3
// speedup vs baseline: 1.4154x; 1.4154x over previous
#include <cuda_runtime.h>

// AtteMatchLay: multi-perspective cosine matching. N=8192 rows, D=768, P=20.
// out[n,p] = dot/(max(sqrt(n1),eps)*max(sqrt(n2),eps)), sums over d weighted by w[p,d]^2.
//
// Mapping: warp = (4 rows) x (10 perspectives). f32x2 packs TWO ROWS.
// Per 64-d iter: 8 data LDG.64 + 10 w2 LDG.64 -> 120 fma2 (ratio 6.7:1).
// w2 traffic amortized 4x over rows; P split in 2 disjoint groups (no w2 duplication).

#define PDIM  20
#define DDIM  768
#define PP    10     // perspectives per warp (P-group size)
#define RROWS 4      // rows per warp
#define NPK   2      // f32x2 row-packs per warp (RROWS/2)
#define EPS   1e-8f

typedef unsigned long long ull;

// ---- packed f32x2 helpers (only reachable via PTX) ----
__device__ __forceinline__ ull pack2(float x) {
    ull r; asm("mov.b64 %0, {%1, %1};" : "=l"(r) : "f"(x)); return r;
}
__device__ __forceinline__ ull packab(float a, float b) {
    ull r; asm("mov.b64 %0, {%1, %2};" : "=l"(r) : "f"(a), "f"(b)); return r;
}
__device__ __forceinline__ float2 u2f(ull v) {
    float2 f; asm("mov.b64 {%0, %1}, %2;" : "=f"(f.x), "=f"(f.y) : "l"(v)); return f;
}
__device__ __forceinline__ ull mul2(ull a, ull b) {
    ull r; asm("mul.rn.f32x2 %0, %1, %2;" : "=l"(r) : "l"(a), "l"(b)); return r;
}
__device__ __forceinline__ void fma2(ull& acc, ull a, ull b) {
    asm("fma.rn.f32x2 %0, %1, %2, %0;" : "+l"(acc) : "l"(a), "l"(b));
}
__device__ __forceinline__ ull add2(ull a, ull b) {
    ull r; asm("add.rn.f32x2 %0, %1, %2;" : "=l"(r) : "l"(a), "l"(b)); return r;
}

// Squared weights, plain [P][D] float layout.
__device__ float g_w2[PDIM * DDIM];

__global__ void prep_w2_kernel(const float* __restrict__ weight) {
    int t = blockIdx.x * blockDim.x + threadIdx.x;
    if (t < PDIM * DDIM) {
        float w = weight[t];
        g_w2[t] = w * w;
    }
}

// Block = 128 threads = 4 warps = 2 row-quads x 2 P-groups -> 8 rows/block.
__global__ void __launch_bounds__(128)
cosmatch_kernel(const float* __restrict__ repres,
                const float* __restrict__ max_att,
                float* __restrict__ out,
                int N) {
    const int tid  = threadIdx.x;
    const int warp = tid >> 5;
    const int lane = tid & 31;
    const int pg   = warp & 1;        // perspective group (0/1)
    const int rq   = warp >> 1;       // row quad within block (0/1)
    const int rowbase = blockIdx.x * 8 + rq * RROWS;
    if (rowbase >= N) return;

    const float* rp = repres  + (size_t)rowbase * DDIM;
    const float* mp = max_att + (size_t)rowbase * DDIM;
    const float* wg = g_w2 + pg * PP * DDIM;

    ull accd[PP][NPK], accr[PP][NPK], accm[PP][NPK];
#pragma unroll
    for (int p = 0; p < PP; p++)
#pragma unroll
        for (int k = 0; k < NPK; k++) {
            accd[p][k] = 0ull; accr[p][k] = 0ull; accm[p][k] = 0ull;
        }

    // 12 iterations of 64 d each; lane owns d = it*64 + 2*lane + {0,1}
#pragma unroll 2
    for (int it = 0; it < DDIM / 64; it++) {
        const int d0 = it * 64 + lane * 2;

        const float2 R0 = *(const float2*)(rp + 0 * DDIM + d0);
        const float2 R1 = *(const float2*)(rp + 1 * DDIM + d0);
        const float2 R2 = *(const float2*)(rp + 2 * DDIM + d0);
        const float2 R3 = *(const float2*)(rp + 3 * DDIM + d0);
        const float2 M0 = *(const float2*)(mp + 0 * DDIM + d0);
        const float2 M1 = *(const float2*)(mp + 1 * DDIM + d0);
        const float2 M2 = *(const float2*)(mp + 2 * DDIM + d0);
        const float2 M3 = *(const float2*)(mp + 3 * DDIM + d0);

        // Row-packed operands: pack k covers rows {2k, 2k+1}; index [dd] = d0+dd
        ull rm[NPK][2], rr[NPK][2], mm[NPK][2];
        {
            ull ra0 = packab(R0.x, R1.x), ra1 = packab(R0.y, R1.y);
            ull ma0 = packab(M0.x, M1.x), ma1 = packab(M0.y, M1.y);
            rm[0][0] = mul2(ra0, ma0);  rm[0][1] = mul2(ra1, ma1);
            rr[0][0] = mul2(ra0, ra0);  rr[0][1] = mul2(ra1, ra1);
            mm[0][0] = mul2(ma0, ma0);  mm[0][1] = mul2(ma1, ma1);
        }
        {
            ull rb0 = packab(R2.x, R3.x), rb1 = packab(R2.y, R3.y);
            ull mb0 = packab(M2.x, M3.x), mb1 = packab(M2.y, M3.y);
            rm[1][0] = mul2(rb0, mb0);  rm[1][1] = mul2(rb1, mb1);
            rr[1][0] = mul2(rb0, rb0);  rr[1][1] = mul2(rb1, rb1);
            mm[1][0] = mul2(mb0, mb0);  mm[1][1] = mul2(mb1, mb1);
        }

#pragma unroll
        for (int p = 0; p < PP; p++) {
            const float2 w = *(const float2*)(wg + p * DDIM + d0);
            const ull wx = pack2(w.x);
            const ull wy = pack2(w.y);
#pragma unroll
            for (int k = 0; k < NPK; k++) {
                fma2(accd[p][k], rm[k][0], wx);
                fma2(accd[p][k], rm[k][1], wy);
                fma2(accr[p][k], rr[k][0], wx);
                fma2(accr[p][k], rr[k][1], wy);
                fma2(accm[p][k], mm[k][0], wx);
                fma2(accm[p][k], mm[k][1], wy);
            }
        }
    }

    // Butterfly reduction across lanes (all accumulators stay row-packed)
#pragma unroll
    for (int mask = 16; mask > 0; mask >>= 1) {
#pragma unroll
        for (int p = 0; p < PP; p++)
#pragma unroll
            for (int k = 0; k < NPK; k++) {
                accd[p][k] = add2(accd[p][k], (ull)__shfl_xor_sync(0xFFFFFFFFu, accd[p][k], mask));
                accr[p][k] = add2(accr[p][k], (ull)__shfl_xor_sync(0xFFFFFFFFu, accr[p][k], mask));
                accm[p][k] = add2(accm[p][k], (ull)__shfl_xor_sync(0xFFFFFFFFu, accm[p][k], mask));
            }
    }

    // Epilogue: lane 0 writes 4 rows x 10 perspectives
    if (lane == 0) {
#pragma unroll
        for (int k = 0; k < NPK; k++) {
            float* o0 = out + (size_t)(rowbase + 2 * k + 0) * PDIM + pg * PP;
            float* o1 = out + (size_t)(rowbase + 2 * k + 1) * PDIM + pg * PP;
#pragma unroll
            for (int p = 0; p < PP; p++) {
                const float2 dd = u2f(accd[p][k]);
                const float2 n1 = u2f(accr[p][k]);
                const float2 n2 = u2f(accm[p][k]);
                o0[p] = dd.x / (fmaxf(sqrtf(n1.x), EPS) * fmaxf(sqrtf(n2.x), EPS));
                o1[p] = dd.y / (fmaxf(sqrtf(n1.y), EPS) * fmaxf(sqrtf(n2.y), EPS));
            }
        }
    }
}

extern "C" void kernel_launch(void* const* d_in, const int* in_sizes, int n_in,
                              void* d_out, int out_size) {
    const float* repres  = (const float*)d_in[0];
    const float* max_att = (const float*)d_in[1];
    const float* weight  = (const float*)d_in[2];
    float* out = (float*)d_out;

    const int N = in_sizes[0] / DDIM;   // 8192 rows for the given shapes

    {
        const int total = PDIM * DDIM;
        prep_w2_kernel<<<(total + 255) / 256, 256>>>(weight);
    }
    {
        // 8 rows per block (4 warps: 2 row-quads x 2 P-groups)
        const int blocks = (N + 7) / 8;
        cosmatch_kernel<<<blocks, 128>>>(repres, max_att, out, N);
    }
}

// round 4
// speedup vs baseline: 1.4860x; 1.0499x over previous
#include <cuda_runtime.h>

// AtteMatchLay: multi-perspective cosine matching. N=8192 rows, D=768, P=20.
// out[n,p] = dot/(max(sqrt(n1),eps)*max(sqrt(n2),eps)), sums over d weighted by w[p,d]^2.
//
// Round-3 shape: warp-tile = 2 rows x 10 perspectives, f32x2 packs the TWO ROWS.
// Accumulators: 10p x 3 sums = 30 f32x2 = 60 regs (was 120) -> ~20 warps/SM occupancy.
// Per 64-d iter: 4 data LDG.64 + 10 w2 LDG.64 -> 60 fma2 + 6 mul2.

#define PDIM  20
#define DDIM  768
#define PP    10     // perspectives per warp (P-group size)
#define EPS   1e-8f

typedef unsigned long long ull;

// ---- packed f32x2 helpers (only reachable via PTX) ----
__device__ __forceinline__ ull pack2(float x) {
    ull r; asm("mov.b64 %0, {%1, %1};" : "=l"(r) : "f"(x)); return r;
}
__device__ __forceinline__ ull packab(float a, float b) {
    ull r; asm("mov.b64 %0, {%1, %2};" : "=l"(r) : "f"(a), "f"(b)); return r;
}
__device__ __forceinline__ float2 u2f(ull v) {
    float2 f; asm("mov.b64 {%0, %1}, %2;" : "=f"(f.x), "=f"(f.y) : "l"(v)); return f;
}
__device__ __forceinline__ ull mul2(ull a, ull b) {
    ull r; asm("mul.rn.f32x2 %0, %1, %2;" : "=l"(r) : "l"(a), "l"(b)); return r;
}
__device__ __forceinline__ void fma2(ull& acc, ull a, ull b) {
    asm("fma.rn.f32x2 %0, %1, %2, %0;" : "+l"(acc) : "l"(a), "l"(b));
}
__device__ __forceinline__ ull add2(ull a, ull b) {
    ull r; asm("add.rn.f32x2 %0, %1, %2;" : "=l"(r) : "l"(a), "l"(b)); return r;
}

// Squared weights, plain [P][D] float layout (61 KB, stays L1/L2 hot).
__device__ float g_w2[PDIM * DDIM];

__global__ void prep_w2_kernel(const float* __restrict__ weight) {
    int t = blockIdx.x * blockDim.x + threadIdx.x;
    if (t < PDIM * DDIM) {
        float w = weight[t];
        g_w2[t] = w * w;
    }
}

// Block = 128 threads = 4 warps = 2 row-pairs x 2 P-groups -> 4 rows/block.
__global__ void __launch_bounds__(128)
cosmatch_kernel(const float* __restrict__ repres,
                const float* __restrict__ max_att,
                float* __restrict__ out,
                int N) {
    const int tid  = threadIdx.x;
    const int warp = tid >> 5;
    const int lane = tid & 31;
    const int pg   = warp & 1;        // perspective group (0/1)
    const int rq   = warp >> 1;       // row pair within block (0/1)
    const int rowbase = blockIdx.x * 4 + rq * 2;
    if (rowbase >= N) return;

    const float* rp = repres  + (size_t)rowbase * DDIM;
    const float* mp = max_att + (size_t)rowbase * DDIM;
    const float* wg = g_w2 + pg * PP * DDIM;

    ull accd[PP], accr[PP], accm[PP];
#pragma unroll
    for (int p = 0; p < PP; p++) { accd[p] = 0ull; accr[p] = 0ull; accm[p] = 0ull; }

    // 12 iterations of 64 d each; lane owns d = it*64 + 2*lane + {0,1}
#pragma unroll 2
    for (int it = 0; it < DDIM / 64; it++) {
        const int d0 = it * 64 + lane * 2;

        const float2 R0 = *(const float2*)(rp + d0);            // row 0
        const float2 R1 = *(const float2*)(rp + DDIM + d0);     // row 1
        const float2 M0 = *(const float2*)(mp + d0);
        const float2 M1 = *(const float2*)(mp + DDIM + d0);

        // Row-packed operands: (row0, row1) for each of the two d values
        const ull ra0 = packab(R0.x, R1.x), ra1 = packab(R0.y, R1.y);
        const ull ma0 = packab(M0.x, M1.x), ma1 = packab(M0.y, M1.y);
        const ull rm0 = mul2(ra0, ma0), rm1 = mul2(ra1, ma1);
        const ull rr0 = mul2(ra0, ra0), rr1 = mul2(ra1, ra1);
        const ull mm0 = mul2(ma0, ma0), mm1 = mul2(ma1, ma1);

#pragma unroll
        for (int p = 0; p < PP; p++) {
            const float2 w = *(const float2*)(wg + p * DDIM + d0);
            const ull wx = pack2(w.x);
            const ull wy = pack2(w.y);
            fma2(accd[p], rm0, wx);
            fma2(accd[p], rm1, wy);
            fma2(accr[p], rr0, wx);
            fma2(accr[p], rr1, wy);
            fma2(accm[p], mm0, wx);
            fma2(accm[p], mm1, wy);
        }
    }

    // Butterfly reduction across lanes (accumulators stay row-packed)
#pragma unroll
    for (int mask = 16; mask > 0; mask >>= 1) {
#pragma unroll
        for (int p = 0; p < PP; p++) {
            accd[p] = add2(accd[p], (ull)__shfl_xor_sync(0xFFFFFFFFu, accd[p], mask));
            accr[p] = add2(accr[p], (ull)__shfl_xor_sync(0xFFFFFFFFu, accr[p], mask));
            accm[p] = add2(accm[p], (ull)__shfl_xor_sync(0xFFFFFFFFu, accm[p], mask));
        }
    }

    // Epilogue: lane 0 writes 2 rows x 10 perspectives
    if (lane == 0) {
        float* o0 = out + (size_t)(rowbase + 0) * PDIM + pg * PP;
        float* o1 = out + (size_t)(rowbase + 1) * PDIM + pg * PP;
#pragma unroll
        for (int p = 0; p < PP; p++) {
            const float2 dd = u2f(accd[p]);
            const float2 n1 = u2f(accr[p]);
            const float2 n2 = u2f(accm[p]);
            o0[p] = dd.x / (fmaxf(sqrtf(n1.x), EPS) * fmaxf(sqrtf(n2.x), EPS));
            o1[p] = dd.y / (fmaxf(sqrtf(n1.y), EPS) * fmaxf(sqrtf(n2.y), EPS));
        }
    }
}

extern "C" void kernel_launch(void* const* d_in, const int* in_sizes, int n_in,
                              void* d_out, int out_size) {
    const float* repres  = (const float*)d_in[0];
    const float* max_att = (const float*)d_in[1];
    const float* weight  = (const float*)d_in[2];
    float* out = (float*)d_out;

    const int N = in_sizes[0] / DDIM;   // 8192 rows for the given shapes

    {
        const int total = PDIM * DDIM;
        prep_w2_kernel<<<(total + 255) / 256, 256>>>(weight);
    }
    {
        // 4 rows per block (4 warps: 2 row-pairs x 2 P-groups)
        const int blocks = (N + 3) / 4;
        cosmatch_kernel<<<blocks, 128>>>(repres, max_att, out, N);
    }
}